// round 6
// baseline (speedup 1.0000x reference)
#include <cuda_runtime.h>
#include <cuda_fp16.h>
#include <cstdint>
#include <cstddef>

// Problem constants (fixed by the dataset)
#define NR    16384
#define NCH   65536
#define NP    16384
#define DIM   64
#define ERC   65536
#define EPASS 65536
#define EN    2048   // D*D/2

// Device scratch (allocation-free rule: __device__ globals)
// g_e is K-MAJOR: g_e[u*2048 + k*64 + d] = e[u, d, k]
__device__ __half g_e  [(size_t)NP  * EN];   // 64 MB
__device__ float g_hin [(size_t)NCH * DIM];  // 16 MB
__device__ float g_hout[(size_t)NCH * DIM];  // 16 MB
__device__ float g_min [(size_t)NCH * 32];   // 8 MB
__device__ float g_mout[(size_t)NCH * 32];   // 8 MB

// Side stream + fork/join events, created once at load time.
struct SideStream {
    cudaStream_t s2;
    cudaEvent_t evFork, evJoin;
    SideStream() {
        cudaStreamCreate(&s2);
        cudaEventCreateWithFlags(&evFork, cudaEventDisableTiming);
        cudaEventCreateWithFlags(&evJoin, cudaEventDisableTiming);
    }
};
static SideStream g_ss;

__device__ __forceinline__ void red_add_v4(float* p, float4 v) {
    asm volatile("red.global.add.v4.f32 [%0], {%1,%2,%3,%4};"
                 :: "l"(p), "f"(v.x), "f"(v.y), "f"(v.z), "f"(v.w) : "memory");
}
__device__ __forceinline__ void red_add_f(float* p, float v) {
    asm volatile("red.global.add.f32 [%0], %1;" :: "l"(p), "f"(v) : "memory");
}
__device__ __forceinline__ uint32_t smem_u32(const void* p) {
    return (uint32_t)__cvta_generic_to_shared(p);
}

// ---------------------------------------------------------------------------
// K0a (main stream): zero hin/hout
__global__ void zero_h_kernel(float4* __restrict__ hin, float4* __restrict__ hout) {
    const int n_h = (NCH * DIM) / 4;
    float4 z = make_float4(0.f, 0.f, 0.f, 0.f);
    int stride = gridDim.x * blockDim.x;
    for (int i = blockIdx.x * blockDim.x + threadIdx.x; i < n_h; i += stride) {
        hin[i] = z; hout[i] = z;
    }
}
// K0b (side stream): zero min/mout/out
__global__ void zero_m_kernel(float4* __restrict__ min_, float4* __restrict__ mout_,
                              float4* __restrict__ out) {
    const int n_m = (NCH * 32) / 4;
    const int n_o = (NR * DIM) / 4;
    float4 z = make_float4(0.f, 0.f, 0.f, 0.f);
    int stride = gridDim.x * blockDim.x;
    for (int i = blockIdx.x * blockDim.x + threadIdx.x; i < n_m; i += stride) {
        min_[i] = z; mout_[i] = z;
    }
    for (int i = blockIdx.x * blockDim.x + threadIdx.x; i < n_o; i += stride) {
        out[i] = z;
    }
}

// ---------------------------------------------------------------------------
// K1: scatter-add h rows along edges: acc[dst[e]] += h[src[e]]  (64 floats/row)
__global__ void scatter_h_kernel(const int* __restrict__ src0, const int* __restrict__ dst0,
                                 const int* __restrict__ src1, const int* __restrict__ dst1,
                                 const float* __restrict__ h,
                                 float* __restrict__ acc0, float* __restrict__ acc1) {
    int tid = blockIdx.x * blockDim.x + threadIdx.x;
    int e = tid >> 4;
    int c = tid & 15;
    const int* src; const int* dst; float* acc;
    if (e < ERC) { src = src0; dst = dst0; acc = acc0; }
    else if (e < 2 * ERC) { e -= ERC; src = src1; dst = dst1; acc = acc1; }
    else return;
    int s = src[e];
    int d = dst[e];
    float4 v = *(const float4*)(h + (size_t)s * DIM + c * 4);
    red_add_v4(acc + (size_t)d * DIM + c * 4, v);
}

// ---------------------------------------------------------------------------
// K2: e = h_packet @ W_p^T + b_p  -> K-MAJOR fp16 output.
// Output col kappa = k*64 + d corresponds to W_p row (d*32 + k): the k-major
// layout is obtained purely by permuting which W_p row feeds each B-tile row.
__global__ void __launch_bounds__(256) gemm_e_hmma(
        const float* __restrict__ A,    // [NP, 64] h_packet
        const float* __restrict__ B,    // [2048, 64] W_p
        const float* __restrict__ bias, // [2048] b_p
        __half* __restrict__ C) {       // [NP, 2048] k-major
    __shared__ __align__(16) __half As[128 * 64];
    __shared__ __align__(16) __half Bs[128 * 64];
    const int t  = threadIdx.x;
    const int m0 = blockIdx.y * 128;
    const int n0 = blockIdx.x * 128;

    {
        const float* G0 = A + (size_t)m0 * DIM;
#pragma unroll
        for (int i = 0; i < 4; i++) {
            int idx = i * 256 + t;      // 0..1023
            int r = idx >> 3, ch = idx & 7;
            int pch = ch ^ (r & 7);
            {
                const float4* gp = (const float4*)(G0 + (size_t)r * DIM + ch * 8);
                float4 lo = gp[0], hi = gp[1];
                __half2 h0 = __floats2half2_rn(lo.x, lo.y);
                __half2 h1 = __floats2half2_rn(lo.z, lo.w);
                __half2 h2 = __floats2half2_rn(hi.x, hi.y);
                __half2 h3 = __floats2half2_rn(hi.z, hi.w);
                uint4 v = make_uint4(*(unsigned*)&h0, *(unsigned*)&h1,
                                     *(unsigned*)&h2, *(unsigned*)&h3);
                *(uint4*)(As + r * 64 + pch * 8) = v;
            }
            {
                int kap = n0 + r;                       // output col
                int brow = (kap & 63) * 32 + (kap >> 6); // permuted W_p row
                const float4* gp = (const float4*)(B + (size_t)brow * DIM + ch * 8);
                float4 lo = gp[0], hi = gp[1];
                __half2 h0 = __floats2half2_rn(lo.x, lo.y);
                __half2 h1 = __floats2half2_rn(lo.z, lo.w);
                __half2 h2 = __floats2half2_rn(hi.x, hi.y);
                __half2 h3 = __floats2half2_rn(hi.z, hi.w);
                uint4 v = make_uint4(*(unsigned*)&h0, *(unsigned*)&h1,
                                     *(unsigned*)&h2, *(unsigned*)&h3);
                *(uint4*)(Bs + r * 64 + pch * 8) = v;
            }
        }
    }
    __syncthreads();

    const int wid  = t >> 5, lane = t & 31;
    const int mbase = (wid >> 2) * 64;   // warp_m in {0,1}
    const int nbase = (wid & 3) * 32;    // warp_n in {0..3}

    float acc[4][4][4];
#pragma unroll
    for (int mt = 0; mt < 4; mt++)
#pragma unroll
        for (int nt = 0; nt < 4; nt++)
#pragma unroll
            for (int j = 0; j < 4; j++) acc[mt][nt][j] = 0.f;

#pragma unroll
    for (int ks = 0; ks < 4; ks++) {
        uint32_t a[4][4], bf[2][4];
        const int lrow = lane & 15;
        const int lch  = 2 * ks + (lane >> 4);
#pragma unroll
        for (int mt = 0; mt < 4; mt++) {
            int r = mbase + mt * 16 + lrow;
            uint32_t addr = smem_u32(As + r * 64 + (lch ^ (r & 7)) * 8);
            asm volatile("ldmatrix.sync.aligned.m8n8.x4.shared.b16 {%0,%1,%2,%3}, [%4];"
                : "=r"(a[mt][0]), "=r"(a[mt][1]), "=r"(a[mt][2]), "=r"(a[mt][3])
                : "r"(addr));
        }
#pragma unroll
        for (int np = 0; np < 2; np++) {
            int r = nbase + np * 16 + lrow;
            uint32_t addr = smem_u32(Bs + r * 64 + (lch ^ (r & 7)) * 8);
            asm volatile("ldmatrix.sync.aligned.m8n8.x4.shared.b16 {%0,%1,%2,%3}, [%4];"
                : "=r"(bf[np][0]), "=r"(bf[np][1]), "=r"(bf[np][2]), "=r"(bf[np][3])
                : "r"(addr));
        }
#pragma unroll
        for (int mt = 0; mt < 4; mt++)
#pragma unroll
            for (int nt = 0; nt < 4; nt++) {
                uint32_t b0 = bf[nt >> 1][nt & 1];
                uint32_t b1 = bf[nt >> 1][2 + (nt & 1)];
                asm volatile(
                    "mma.sync.aligned.m16n8k16.row.col.f32.f16.f16.f32 "
                    "{%0,%1,%2,%3}, {%4,%5,%6,%7}, {%8,%9}, {%0,%1,%2,%3};"
                    : "+f"(acc[mt][nt][0]), "+f"(acc[mt][nt][1]),
                      "+f"(acc[mt][nt][2]), "+f"(acc[mt][nt][3])
                    : "r"(a[mt][0]), "r"(a[mt][1]), "r"(a[mt][2]), "r"(a[mt][3]),
                      "r"(b0), "r"(b1));
            }
    }

    const int row_l = lane >> 2;
    const int col_l = (lane & 3) * 2;
#pragma unroll
    for (int mt = 0; mt < 4; mt++) {
        int m = m0 + mbase + mt * 16 + row_l;
#pragma unroll
        for (int nt = 0; nt < 4; nt++) {
            int kap = n0 + nbase + nt * 8 + col_l;   // even; kap+1 = d+1, same k
            int b0row = (kap & 63) * 32 + (kap >> 6);
            float bx = bias[b0row];
            float by = bias[b0row + 32];             // row for d+1
            __half2 h01 = __floats2half2_rn(acc[mt][nt][0] + bx,
                                            acc[mt][nt][1] + by);
            __half2 h23 = __floats2half2_rn(acc[mt][nt][2] + bx,
                                            acc[mt][nt][3] + by);
            *(__half2*)(C + (size_t)m * EN + kap)       = h01;
            *(__half2*)(C + (size_t)(m + 8) * EN + kap) = h23;
        }
    }
}

// ---------------------------------------------------------------------------
// K3: pass edges, k-major e. One warp per edge; lane = k (0..31):
//   m_in[v,k]  = sum_d e_k[u, k*64+d] * h_in[v,d]   (same for m_out)
// 8x LDG.128 per edge; h broadcast as packed half2 via shfl; HFMA2 chunk
// accumulation (8 terms) upconverted to f32 each chunk. No cross-lane reduce.
__global__ void pass_kernel(
        const int* __restrict__ psrc, const int* __restrict__ pdst,
        const __half* __restrict__ ek,
        const float* __restrict__ hin, const float* __restrict__ hout,
        float* __restrict__ min_, float* __restrict__ mout_) {
    int gtid = blockIdx.x * blockDim.x + threadIdx.x;
    int w    = gtid >> 5;
    int lane = gtid & 31;
    if (w >= EPASS) return;
    int u = psrc[w];
    int v = pdst[w];

    // packed h: lane j holds (h[2j], h[2j+1]) as half2
    float2 fi = *(const float2*)(hin  + (size_t)v * DIM + 2 * lane);
    float2 fo = *(const float2*)(hout + (size_t)v * DIM + 2 * lane);
    __half2 phi = __floats2half2_rn(fi.x, fi.y);
    __half2 pho = __floats2half2_rn(fo.x, fo.y);
    unsigned phiu = *(unsigned*)&phi;
    unsigned phou = *(unsigned*)&pho;

    const float4* ev4 = (const float4*)(ek + (size_t)u * EN) + lane * 8;

    float mi = 0.f, mo = 0.f;
#pragma unroll
    for (int c = 0; c < 8; c++) {               // d chunk = [8c, 8c+8)
        float4 evc = ev4[c];
        const __half2* ep = (const __half2*)&evc;  // 4 half2: d pairs
        __half2 acci, acco;
#pragma unroll
        for (int tt = 0; tt < 4; tt++) {
            unsigned hiu = __shfl_sync(0xffffffffu, phiu, 4 * c + tt);
            unsigned hou = __shfl_sync(0xffffffffu, phou, 4 * c + tt);
            __half2 hih = *(__half2*)&hiu;
            __half2 hoh = *(__half2*)&hou;
            if (tt == 0) { acci = __hmul2(ep[0], hih); acco = __hmul2(ep[0], hoh); }
            else         { acci = __hfma2(ep[tt], hih, acci);
                           acco = __hfma2(ep[tt], hoh, acco); }
        }
        float2 ai = __half22float2(acci);
        float2 ao = __half22float2(acco);
        mi += ai.x + ai.y;
        mo += ao.x + ao.y;
    }

    red_add_f(min_  + (size_t)v * 32 + lane, mi);
    red_add_f(mout_ + (size_t)v * 32 + lane, mo);
}

// ---------------------------------------------------------------------------
// K4: gather channel -> router into d_out. 8 lanes per edge, float4 chunks.
__global__ void gather_kernel(const int* __restrict__ isrc, const int* __restrict__ idst,
                              const int* __restrict__ oisrc, const int* __restrict__ oidst,
                              const float* __restrict__ min_, const float* __restrict__ mout_,
                              float* __restrict__ out) {
    int gtid = blockIdx.x * blockDim.x + threadIdx.x;
    int e = gtid >> 3;
    int c = gtid & 7;
    if (e < ERC) {
        int s = isrc[e], d = idst[e];
        float4 v = *(const float4*)(min_ + (size_t)s * 32 + c * 4);
        red_add_v4(out + (size_t)d * DIM + c * 4, v);
    } else if (e < 2 * ERC) {
        int ee = e - ERC;
        int s = oisrc[ee], d = oidst[ee];
        float4 v = *(const float4*)(mout_ + (size_t)s * 32 + c * 4);
        red_add_v4(out + (size_t)d * DIM + 32 + c * 4, v);
    }
}

// ---------------------------------------------------------------------------
// K5: relu epilogue on out
__global__ void relu_kernel(float4* __restrict__ out) {
    int i = blockIdx.x * blockDim.x + threadIdx.x;
    float4 v = out[i];
    v.x = fmaxf(v.x, 0.f); v.y = fmaxf(v.y, 0.f);
    v.z = fmaxf(v.z, 0.f); v.w = fmaxf(v.w, 0.f);
    out[i] = v;
}

// ===========================================================================
extern "C" void kernel_launch(void* const* d_in, const int* in_sizes, int n_in,
                              void* d_out, int out_size) {
    const float* h_router       = (const float*)d_in[0];
    const float* h_packet       = (const float*)d_in[1];
    const float* W_p            = (const float*)d_in[2];
    const float* b_p            = (const float*)d_in[3];
    // d_in[4] = W_c, d_in[5] = b_c : dead code in reference
    const int* output_src       = (const int*)d_in[6];
    const int* output_dst       = (const int*)d_in[7];
    const int* input_inv_src    = (const int*)d_in[8];
    const int* input_inv_dst    = (const int*)d_in[9];
    const int* pass_src         = (const int*)d_in[10];
    const int* pass_dst         = (const int*)d_in[11];
    const int* input_src        = (const int*)d_in[12];
    const int* input_dst        = (const int*)d_in[13];
    const int* output_inv_src   = (const int*)d_in[14];
    const int* output_inv_dst   = (const int*)d_in[15];
    float* out = (float*)d_out;

    __half* p_e;
    float *p_hin, *p_hout, *p_min, *p_mout;
    cudaGetSymbolAddress((void**)&p_e,    g_e);
    cudaGetSymbolAddress((void**)&p_hin,  g_hin);
    cudaGetSymbolAddress((void**)&p_hout, g_hout);
    cudaGetSymbolAddress((void**)&p_min,  g_min);
    cudaGetSymbolAddress((void**)&p_mout, g_mout);

    // Fork: side stream zeroes pass/gather outputs, then runs the GEMM —
    // all independent of the hin/hout zero+scatter chain on the main stream.
    cudaEventRecord(g_ss.evFork, 0);
    cudaStreamWaitEvent(g_ss.s2, g_ss.evFork, 0);
    zero_m_kernel<<<1024, 256, 0, g_ss.s2>>>((float4*)p_min, (float4*)p_mout,
                                             (float4*)out);
    {
        dim3 grid(EN / 128, NP / 128);  // (16, 128)
        gemm_e_hmma<<<grid, 256, 0, g_ss.s2>>>(h_packet, W_p, b_p, p_e);
    }
    cudaEventRecord(g_ss.evJoin, g_ss.s2);

    // Main stream: zero hin/hout, then router->channel scatters
    zero_h_kernel<<<2048, 256>>>((float4*)p_hin, (float4*)p_hout);
    scatter_h_kernel<<<(2 * ERC * 16) / 256, 256>>>(
        output_src, output_dst, input_inv_src, input_inv_dst,
        h_router, p_hin, p_hout);

    // Join: pass needs the GEMM output, zeroed m buffers, and scattered h
    cudaStreamWaitEvent(0, g_ss.evJoin, 0);

    // pass edges: warp per edge, lane = k
    pass_kernel<<<(EPASS * 32) / 256, 256>>>(pass_src, pass_dst, p_e,
                                             p_hin, p_hout, p_min, p_mout);

    // channel -> router gathers into out (8 lanes/edge, vectorized)
    gather_kernel<<<(2 * ERC * 8) / 256, 256>>>(input_src, input_dst,
                                                output_inv_src, output_inv_dst,
                                                p_min, p_mout, out);

    // relu epilogue
    relu_kernel<<<(NR * DIM) / (4 * 256), 256>>>((float4*)out);
}

// round 7
// speedup vs baseline: 1.4492x; 1.4492x over previous
#include <cuda_runtime.h>
#include <cuda_fp16.h>
#include <cstdint>
#include <cstddef>

// Problem constants (fixed by the dataset)
#define NR    16384
#define NCH   65536
#define NP    16384
#define DIM   64
#define ERC   65536
#define EPASS 65536
#define EN    2048   // D*D/2

// Device scratch (allocation-free rule: __device__ globals)
// g_e TILED layout: addr(u,k,d) = u*2048 + (d>>3)*256 + k*8 + (d&7)
//   -> lane k's chunk c (d in [8c,8c+8)) is the float4 at (u*256 + c*32 + k)
__device__ __half g_e  [(size_t)NP  * EN];   // 64 MB
__device__ float g_hin [(size_t)NCH * DIM];  // 16 MB
__device__ float g_hout[(size_t)NCH * DIM];  // 16 MB
__device__ float g_min [(size_t)NCH * 32];   // 8 MB
__device__ float g_mout[(size_t)NCH * 32];   // 8 MB

// Side stream + fork/join events, created once at load time.
struct SideStream {
    cudaStream_t s2;
    cudaEvent_t evFork, evJoin;
    SideStream() {
        cudaStreamCreate(&s2);
        cudaEventCreateWithFlags(&evFork, cudaEventDisableTiming);
        cudaEventCreateWithFlags(&evJoin, cudaEventDisableTiming);
    }
};
static SideStream g_ss;

__device__ __forceinline__ void red_add_v4(float* p, float4 v) {
    asm volatile("red.global.add.v4.f32 [%0], {%1,%2,%3,%4};"
                 :: "l"(p), "f"(v.x), "f"(v.y), "f"(v.z), "f"(v.w) : "memory");
}
__device__ __forceinline__ void red_add_f(float* p, float v) {
    asm volatile("red.global.add.f32 [%0], %1;" :: "l"(p), "f"(v) : "memory");
}
__device__ __forceinline__ uint32_t smem_u32(const void* p) {
    return (uint32_t)__cvta_generic_to_shared(p);
}

// Map a storage column n (0..2047) to its W_p row: n = c*256 + k*8 + dd,
// d = 8c + dd, W_p row = d*32 + k.
__device__ __forceinline__ int wp_row_of_col(int n) {
    int dd = n & 7;
    int k  = (n >> 3) & 31;
    int c  = n >> 8;
    return (8 * c + dd) * 32 + k;
}

// ---------------------------------------------------------------------------
// K0a (main stream): zero hin/hout
__global__ void zero_h_kernel(float4* __restrict__ hin, float4* __restrict__ hout) {
    const int n_h = (NCH * DIM) / 4;
    float4 z = make_float4(0.f, 0.f, 0.f, 0.f);
    int stride = gridDim.x * blockDim.x;
    for (int i = blockIdx.x * blockDim.x + threadIdx.x; i < n_h; i += stride) {
        hin[i] = z; hout[i] = z;
    }
}
// K0b (side stream): zero min/mout/out
__global__ void zero_m_kernel(float4* __restrict__ min_, float4* __restrict__ mout_,
                              float4* __restrict__ out) {
    const int n_m = (NCH * 32) / 4;
    const int n_o = (NR * DIM) / 4;
    float4 z = make_float4(0.f, 0.f, 0.f, 0.f);
    int stride = gridDim.x * blockDim.x;
    for (int i = blockIdx.x * blockDim.x + threadIdx.x; i < n_m; i += stride) {
        min_[i] = z; mout_[i] = z;
    }
    for (int i = blockIdx.x * blockDim.x + threadIdx.x; i < n_o; i += stride) {
        out[i] = z;
    }
}

// ---------------------------------------------------------------------------
// K1: scatter-add h rows along edges: acc[dst[e]] += h[src[e]]  (64 floats/row)
__global__ void scatter_h_kernel(const int* __restrict__ src0, const int* __restrict__ dst0,
                                 const int* __restrict__ src1, const int* __restrict__ dst1,
                                 const float* __restrict__ h,
                                 float* __restrict__ acc0, float* __restrict__ acc1) {
    int tid = blockIdx.x * blockDim.x + threadIdx.x;
    int e = tid >> 4;
    int c = tid & 15;
    const int* src; const int* dst; float* acc;
    if (e < ERC) { src = src0; dst = dst0; acc = acc0; }
    else if (e < 2 * ERC) { e -= ERC; src = src1; dst = dst1; acc = acc1; }
    else return;
    int s = src[e];
    int d = dst[e];
    float4 v = *(const float4*)(h + (size_t)s * DIM + c * 4);
    red_add_v4(acc + (size_t)d * DIM + c * 4, v);
}

// ---------------------------------------------------------------------------
// K2: e = h_packet @ W_p^T + b_p  -> TILED fp16 output (see g_e comment).
// Storage col n reads W_p row wp_row_of_col(n): the layout is obtained by
// permuting which W_p row feeds each B-tile row. Epilogue half2 stores stay
// contiguous (col pairs (n, n+1) share k, differ in d by 1 within a chunk).
__global__ void __launch_bounds__(256) gemm_e_hmma(
        const float* __restrict__ A,    // [NP, 64] h_packet
        const float* __restrict__ B,    // [2048, 64] W_p
        const float* __restrict__ bias, // [2048] b_p
        __half* __restrict__ C) {       // [NP, 2048] tiled
    __shared__ __align__(16) __half As[128 * 64];
    __shared__ __align__(16) __half Bs[128 * 64];
    const int t  = threadIdx.x;
    const int m0 = blockIdx.y * 128;
    const int n0 = blockIdx.x * 128;

    {
        const float* G0 = A + (size_t)m0 * DIM;
#pragma unroll
        for (int i = 0; i < 4; i++) {
            int idx = i * 256 + t;      // 0..1023
            int r = idx >> 3, ch = idx & 7;
            int pch = ch ^ (r & 7);
            {
                const float4* gp = (const float4*)(G0 + (size_t)r * DIM + ch * 8);
                float4 lo = gp[0], hi = gp[1];
                __half2 h0 = __floats2half2_rn(lo.x, lo.y);
                __half2 h1 = __floats2half2_rn(lo.z, lo.w);
                __half2 h2 = __floats2half2_rn(hi.x, hi.y);
                __half2 h3 = __floats2half2_rn(hi.z, hi.w);
                uint4 v = make_uint4(*(unsigned*)&h0, *(unsigned*)&h1,
                                     *(unsigned*)&h2, *(unsigned*)&h3);
                *(uint4*)(As + r * 64 + pch * 8) = v;
            }
            {
                int brow = wp_row_of_col(n0 + r);   // permuted W_p row
                const float4* gp = (const float4*)(B + (size_t)brow * DIM + ch * 8);
                float4 lo = gp[0], hi = gp[1];
                __half2 h0 = __floats2half2_rn(lo.x, lo.y);
                __half2 h1 = __floats2half2_rn(lo.z, lo.w);
                __half2 h2 = __floats2half2_rn(hi.x, hi.y);
                __half2 h3 = __floats2half2_rn(hi.z, hi.w);
                uint4 v = make_uint4(*(unsigned*)&h0, *(unsigned*)&h1,
                                     *(unsigned*)&h2, *(unsigned*)&h3);
                *(uint4*)(Bs + r * 64 + pch * 8) = v;
            }
        }
    }
    __syncthreads();

    const int wid  = t >> 5, lane = t & 31;
    const int mbase = (wid >> 2) * 64;   // warp_m in {0,1}
    const int nbase = (wid & 3) * 32;    // warp_n in {0..3}

    float acc[4][4][4];
#pragma unroll
    for (int mt = 0; mt < 4; mt++)
#pragma unroll
        for (int nt = 0; nt < 4; nt++)
#pragma unroll
            for (int j = 0; j < 4; j++) acc[mt][nt][j] = 0.f;

#pragma unroll
    for (int ks = 0; ks < 4; ks++) {
        uint32_t a[4][4], bf[2][4];
        const int lrow = lane & 15;
        const int lch  = 2 * ks + (lane >> 4);
#pragma unroll
        for (int mt = 0; mt < 4; mt++) {
            int r = mbase + mt * 16 + lrow;
            uint32_t addr = smem_u32(As + r * 64 + (lch ^ (r & 7)) * 8);
            asm volatile("ldmatrix.sync.aligned.m8n8.x4.shared.b16 {%0,%1,%2,%3}, [%4];"
                : "=r"(a[mt][0]), "=r"(a[mt][1]), "=r"(a[mt][2]), "=r"(a[mt][3])
                : "r"(addr));
        }
#pragma unroll
        for (int np = 0; np < 2; np++) {
            int r = nbase + np * 16 + lrow;
            uint32_t addr = smem_u32(Bs + r * 64 + (lch ^ (r & 7)) * 8);
            asm volatile("ldmatrix.sync.aligned.m8n8.x4.shared.b16 {%0,%1,%2,%3}, [%4];"
                : "=r"(bf[np][0]), "=r"(bf[np][1]), "=r"(bf[np][2]), "=r"(bf[np][3])
                : "r"(addr));
        }
#pragma unroll
        for (int mt = 0; mt < 4; mt++)
#pragma unroll
            for (int nt = 0; nt < 4; nt++) {
                uint32_t b0 = bf[nt >> 1][nt & 1];
                uint32_t b1 = bf[nt >> 1][2 + (nt & 1)];
                asm volatile(
                    "mma.sync.aligned.m16n8k16.row.col.f32.f16.f16.f32 "
                    "{%0,%1,%2,%3}, {%4,%5,%6,%7}, {%8,%9}, {%0,%1,%2,%3};"
                    : "+f"(acc[mt][nt][0]), "+f"(acc[mt][nt][1]),
                      "+f"(acc[mt][nt][2]), "+f"(acc[mt][nt][3])
                    : "r"(a[mt][0]), "r"(a[mt][1]), "r"(a[mt][2]), "r"(a[mt][3]),
                      "r"(b0), "r"(b1));
            }
    }

    const int row_l = lane >> 2;
    const int col_l = (lane & 3) * 2;
#pragma unroll
    for (int mt = 0; mt < 4; mt++) {
        int m = m0 + mbase + mt * 16 + row_l;
#pragma unroll
        for (int nt = 0; nt < 4; nt++) {
            int n = n0 + nbase + nt * 8 + col_l;   // even, n&7 <= 6
            int b0row = wp_row_of_col(n);
            float bx = bias[b0row];
            float by = bias[b0row + 32];           // col n+1: d+1 -> row+32
            __half2 h01 = __floats2half2_rn(acc[mt][nt][0] + bx,
                                            acc[mt][nt][1] + by);
            __half2 h23 = __floats2half2_rn(acc[mt][nt][2] + bx,
                                            acc[mt][nt][3] + by);
            *(__half2*)(C + (size_t)m * EN + n)       = h01;
            *(__half2*)(C + (size_t)(m + 8) * EN + n) = h23;
        }
    }
}

// ---------------------------------------------------------------------------
// K3: pass edges, tiled e. One warp per edge; lane = k (0..31):
//   m_in[v,k]  = sum_d e[u,k,d] * h_in[v,d]   (same for m_out)
// Chunk c: coalesced LDG.128 at (u*256 + c*32 + lane) float4s; h broadcast
// as packed half2 via shfl; HFMA2 chunk accumulation upconverted to f32
// each 8 terms. No cross-lane reduce; scalar red per lane.
__global__ void pass_kernel(
        const int* __restrict__ psrc, const int* __restrict__ pdst,
        const __half* __restrict__ ek,
        const float* __restrict__ hin, const float* __restrict__ hout,
        float* __restrict__ min_, float* __restrict__ mout_) {
    int gtid = blockIdx.x * blockDim.x + threadIdx.x;
    int w    = gtid >> 5;
    int lane = gtid & 31;
    if (w >= EPASS) return;
    int u = psrc[w];
    int v = pdst[w];

    // packed h: lane j holds (h[2j], h[2j+1]) as half2
    float2 fi = *(const float2*)(hin  + (size_t)v * DIM + 2 * lane);
    float2 fo = *(const float2*)(hout + (size_t)v * DIM + 2 * lane);
    __half2 phi = __floats2half2_rn(fi.x, fi.y);
    __half2 pho = __floats2half2_rn(fo.x, fo.y);
    unsigned phiu = *(unsigned*)&phi;
    unsigned phou = *(unsigned*)&pho;

    const float4* ev4 = (const float4*)(ek + (size_t)u * EN) + lane;

    float mi = 0.f, mo = 0.f;
#pragma unroll
    for (int c = 0; c < 8; c++) {               // d chunk = [8c, 8c+8)
        float4 evc = ev4[c * 32];               // coalesced across lanes
        const __half2* ep = (const __half2*)&evc;  // 4 half2: d pairs
        __half2 acci, acco;
#pragma unroll
        for (int tt = 0; tt < 4; tt++) {
            unsigned hiu = __shfl_sync(0xffffffffu, phiu, 4 * c + tt);
            unsigned hou = __shfl_sync(0xffffffffu, phou, 4 * c + tt);
            __half2 hih = *(__half2*)&hiu;
            __half2 hoh = *(__half2*)&hou;
            if (tt == 0) { acci = __hmul2(ep[0], hih); acco = __hmul2(ep[0], hoh); }
            else         { acci = __hfma2(ep[tt], hih, acci);
                           acco = __hfma2(ep[tt], hoh, acco); }
        }
        float2 ai = __half22float2(acci);
        float2 ao = __half22float2(acco);
        mi += ai.x + ai.y;
        mo += ao.x + ao.y;
    }

    red_add_f(min_  + (size_t)v * 32 + lane, mi);
    red_add_f(mout_ + (size_t)v * 32 + lane, mo);
}

// ---------------------------------------------------------------------------
// K4: gather channel -> router into d_out. 8 lanes per edge, float4 chunks.
__global__ void gather_kernel(const int* __restrict__ isrc, const int* __restrict__ idst,
                              const int* __restrict__ oisrc, const int* __restrict__ oidst,
                              const float* __restrict__ min_, const float* __restrict__ mout_,
                              float* __restrict__ out) {
    int gtid = blockIdx.x * blockDim.x + threadIdx.x;
    int e = gtid >> 3;
    int c = gtid & 7;
    if (e < ERC) {
        int s = isrc[e], d = idst[e];
        float4 v = *(const float4*)(min_ + (size_t)s * 32 + c * 4);
        red_add_v4(out + (size_t)d * DIM + c * 4, v);
    } else if (e < 2 * ERC) {
        int ee = e - ERC;
        int s = oisrc[ee], d = oidst[ee];
        float4 v = *(const float4*)(mout_ + (size_t)s * 32 + c * 4);
        red_add_v4(out + (size_t)d * DIM + 32 + c * 4, v);
    }
}

// ---------------------------------------------------------------------------
// K5: relu epilogue on out
__global__ void relu_kernel(float4* __restrict__ out) {
    int i = blockIdx.x * blockDim.x + threadIdx.x;
    float4 v = out[i];
    v.x = fmaxf(v.x, 0.f); v.y = fmaxf(v.y, 0.f);
    v.z = fmaxf(v.z, 0.f); v.w = fmaxf(v.w, 0.f);
    out[i] = v;
}

// ===========================================================================
extern "C" void kernel_launch(void* const* d_in, const int* in_sizes, int n_in,
                              void* d_out, int out_size) {
    const float* h_router       = (const float*)d_in[0];
    const float* h_packet       = (const float*)d_in[1];
    const float* W_p            = (const float*)d_in[2];
    const float* b_p            = (const float*)d_in[3];
    // d_in[4] = W_c, d_in[5] = b_c : dead code in reference
    const int* output_src       = (const int*)d_in[6];
    const int* output_dst       = (const int*)d_in[7];
    const int* input_inv_src    = (const int*)d_in[8];
    const int* input_inv_dst    = (const int*)d_in[9];
    const int* pass_src         = (const int*)d_in[10];
    const int* pass_dst         = (const int*)d_in[11];
    const int* input_src        = (const int*)d_in[12];
    const int* input_dst        = (const int*)d_in[13];
    const int* output_inv_src   = (const int*)d_in[14];
    const int* output_inv_dst   = (const int*)d_in[15];
    float* out = (float*)d_out;

    __half* p_e;
    float *p_hin, *p_hout, *p_min, *p_mout;
    cudaGetSymbolAddress((void**)&p_e,    g_e);
    cudaGetSymbolAddress((void**)&p_hin,  g_hin);
    cudaGetSymbolAddress((void**)&p_hout, g_hout);
    cudaGetSymbolAddress((void**)&p_min,  g_min);
    cudaGetSymbolAddress((void**)&p_mout, g_mout);

    // Fork: side stream zeroes pass/gather outputs, then runs the GEMM —
    // all independent of the hin/hout zero+scatter chain on the main stream.
    cudaEventRecord(g_ss.evFork, 0);
    cudaStreamWaitEvent(g_ss.s2, g_ss.evFork, 0);
    zero_m_kernel<<<1024, 256, 0, g_ss.s2>>>((float4*)p_min, (float4*)p_mout,
                                             (float4*)out);
    {
        dim3 grid(EN / 128, NP / 128);  // (16, 128)
        gemm_e_hmma<<<grid, 256, 0, g_ss.s2>>>(h_packet, W_p, b_p, p_e);
    }
    cudaEventRecord(g_ss.evJoin, g_ss.s2);

    // Main stream: zero hin/hout, then router->channel scatters
    zero_h_kernel<<<2048, 256>>>((float4*)p_hin, (float4*)p_hout);
    scatter_h_kernel<<<(2 * ERC * 16) / 256, 256>>>(
        output_src, output_dst, input_inv_src, input_inv_dst,
        h_router, p_hin, p_hout);

    // Join: pass needs the GEMM output, zeroed m buffers, and scattered h
    cudaStreamWaitEvent(0, g_ss.evJoin, 0);

    // pass edges: warp per edge, lane = k
    pass_kernel<<<(EPASS * 32) / 256, 256>>>(pass_src, pass_dst, p_e,
                                             p_hin, p_hout, p_min, p_mout);

    // channel -> router gathers into out (8 lanes/edge, vectorized)
    gather_kernel<<<(2 * ERC * 8) / 256, 256>>>(input_src, input_dst,
                                                output_inv_src, output_inv_dst,
                                                p_min, p_mout, out);

    // relu epilogue
    relu_kernel<<<(NR * DIM) / (4 * 256), 256>>>((float4*)out);
}